// round 5
// baseline (speedup 1.0000x reference)
#include <cuda_runtime.h>
#include <cstdint>
#include <cstddef>

#define S_TOK 65536
#define HDIM 768
#define TT 6
#define KK 3
#define WIN 15
#define GRID1 152
#define NTHREAD 512
#define NWARP 16
#define GROUPS (S_TOK/4)

// ---- static scratch ----
__device__ float g_end [S_TOK*8];       // end scores, [s][t] padded to 8
__device__ float g_z  [GRID1*TT];       // per-block sum exp(x)
__device__ float g_t3v[GRID1*TT*3];
__device__ int   g_t3i[GRID1*TT*3];
__device__ float g_y  [GRID1*64];       // per-block W1 GEMV partials (unscaled)
__device__ unsigned g_ctr;

__device__ __forceinline__ void fma2(unsigned long long &d, unsigned long long a, unsigned long long b){
    asm("fma.rn.f32x2 %0, %1, %2, %0;" : "+l"(d) : "l"(a), "l"(b));
}
__device__ __forceinline__ float lo2(unsigned long long u){ return __uint_as_float((unsigned)(u & 0xffffffffull)); }
__device__ __forceinline__ float hi2(unsigned long long u){ return __uint_as_float((unsigned)(u >> 32)); }
__device__ __forceinline__ bool better(float v,int i,float V,int I){ return (v>V)||(v==V && i<I); }
__device__ __forceinline__ void pfL2(const void* p){
    asm volatile("prefetch.global.L2 [%0];" :: "l"(p));
}
// predicated packed pool accumulate (no divergence, no BSSY)
__device__ __forceinline__ void pooladd(unsigned long long &p0, unsigned long long &p1,
    unsigned long long c0x, unsigned long long c0y, unsigned long long c1x, unsigned long long c1y,
    unsigned long long c2x, unsigned long long c2y, unsigned long long c3x, unsigned long long c3y,
    unsigned take)
{
    asm volatile("{\n\t.reg .pred p;\n\tsetp.ne.u32 p, %10, 0;\n\t"
      "@p add.rn.f32x2 %0, %0, %2;\n\t@p add.rn.f32x2 %0, %0, %4;\n\t"
      "@p add.rn.f32x2 %0, %0, %6;\n\t@p add.rn.f32x2 %0, %0, %8;\n\t"
      "@p add.rn.f32x2 %1, %1, %3;\n\t@p add.rn.f32x2 %1, %1, %5;\n\t"
      "@p add.rn.f32x2 %1, %1, %7;\n\t@p add.rn.f32x2 %1, %1, %9;\n\t}"
      : "+l"(p0), "+l"(p1)
      : "l"(c0x),"l"(c0y),"l"(c1x),"l"(c1y),"l"(c2x),"l"(c2y),"l"(c3x),"l"(c3y),"r"(take));
}

#define INS3(x,id) do{ \
    if     (better((x),(id),m0,j0)){ m2=m1;j2=j1; m1=m0;j1=j0; m0=(x);j0=(id); } \
    else if(better((x),(id),m1,j1)){ m2=m1;j2=j1; m1=(x);j1=(id); } \
    else if(better((x),(id),m2,j2)){ m2=(x);j2=(id); } }while(0)

__global__ __launch_bounds__(NTHREAD,1) void k1(
    const float* __restrict__ emb, const float* __restrict__ Wst,
    const float* __restrict__ Wen, const float* __restrict__ W1,
    const float* __restrict__ b1,  const float* __restrict__ W2,
    const float* __restrict__ b2,  float* __restrict__ out, int out_size)
{
    __shared__ __align__(16) float sW[12*HDIM];   // weights; later reused as pool staging (12 slots)
    __shared__ float sbuf[NWARP][24];
    __shared__ float sZ[NWARP][TT];
    __shared__ float sT3v[NWARP][TT][3];
    __shared__ int   sT3i[NWARP][TT][3];
    __shared__ float yred[NTHREAD];
    __shared__ float hbuf[64];
    __shared__ float tc[TT], fZ[TT], fV[TT][3];
    __shared__ int   fI[TT][3];
    __shared__ unsigned slast;

    const int tid = threadIdx.x, w = tid>>5, lane = tid&31;
    const int half = lane>>4, hl = lane&15;
    const int hb3=(hl>>3)&1, hb2=(hl>>2)&1, hb1=(hl>>1)&1, hb0=hl&1;
    const int rowown = hb3*2+hb2;
    const int down   = hb1*3 + (hb0?2:0);
    const unsigned take0 = (half==0)?1u:0u, take1 = 1u-take0;

    // weights transposed: sW[d*768+h]; d 0..5 start, 6..11 end
    for(int i=tid;i<HDIM*TT;i+=NTHREAD){
        int h=i/TT, t=i-h*TT;
        sW[t*HDIM+h]      = Wst[i];
        sW[(TT+t)*HDIM+h] = Wen[i];
    }
    __syncthreads();

    unsigned long long pool[12];
    #pragma unroll
    for(int i=0;i<12;i++) pool[i]=0ull;
    float zv=0.f;
    float v0=-3.4e38f,v1=-3.4e38f,v2=-3.4e38f;
    int i0=0x7fffffff,i1=0x7fffffff,i2=0x7fffffff;

    const float* wbase = sW + (half*6)*HDIM + (hl<<2);
    const int gw = blockIdx.x*NWARP + w;
    const int nw = GRID1*NWARP;

    for(int g=gw; g<GROUPS; g+=nw){
        const int r0=g*4;
        const float* cb = emb + (size_t)g*(4*HDIM) + (hl<<2);
        const int gn = (g+nw<GROUPS)? g+nw : g;
        const float* nb = emb + (size_t)gn*(4*HDIM) + (hl<<2);

        #pragma unroll
        for(int c=0;c<12;c++){
            pfL2(nb + c*64);
            pfL2(nb + HDIM   + c*64);
            pfL2(nb + 2*HDIM + c*64);
            pfL2(nb + 3*HDIM + c*64);
        }

        unsigned long long a[24];
        #pragma unroll
        for(int i=0;i<24;i++) a[i]=0ull;

        #pragma unroll
        for(int c=0;c<12;c++){
            const float* cp = cb + c*64;
            ulonglong2 C0=*(const ulonglong2*)(cp);
            ulonglong2 C1=*(const ulonglong2*)(cp+HDIM);
            ulonglong2 C2=*(const ulonglong2*)(cp+2*HDIM);
            ulonglong2 C3=*(const ulonglong2*)(cp+3*HDIM);

            const int pidx = (c<6)? c : c-6;
            pooladd(pool[2*pidx], pool[2*pidx+1],
                    C0.x,C0.y, C1.x,C1.y, C2.x,C2.y, C3.x,C3.y,
                    (c<6)? take0 : take1);

            const float* wp = wbase + c*64;
            #pragma unroll
            for(int dd=0;dd<6;dd++){
                ulonglong2 W=*(const ulonglong2*)(wp + dd*HDIM);
                fma2(a[dd],    C0.x,W.x); fma2(a[dd],    C0.y,W.y);
                fma2(a[6+dd],  C1.x,W.x); fma2(a[6+dd],  C1.y,W.y);
                fma2(a[12+dd], C2.x,W.x); fma2(a[12+dd], C2.y,W.y);
                fma2(a[18+dd], C3.x,W.x); fma2(a[18+dd], C3.y,W.y);
            }
        }

        float v[24];
        #pragma unroll
        for(int i=0;i<24;i++) v[i]=lo2(a[i])+hi2(a[i]);

        // 16-lane ragged butterfly: 24 -> 12 -> 6 -> 3 -> {2,1}
        #pragma unroll
        for(int i=0;i<12;i++){ float s=hb3? v[i]:v[i+12]; float r=__shfl_xor_sync(0xffffffffu,s,8); v[i]=(hb3? v[i+12]:v[i])+r; }
        #pragma unroll
        for(int i=0;i<6;i++){  float s=hb2? v[i]:v[i+6];  float r=__shfl_xor_sync(0xffffffffu,s,4); v[i]=(hb2? v[i+6]:v[i])+r; }
        #pragma unroll
        for(int i=0;i<3;i++){  float s=hb1? v[i]:v[i+3];  float r=__shfl_xor_sync(0xffffffffu,s,2); v[i]=(hb1? v[i+3]:v[i])+r; }
        {
            float s =hb0? v[0]:v[2]; float r =__shfl_xor_sync(0xffffffffu,s,1);
            float r2=__shfl_xor_sync(0xffffffffu,v[1],1);
            v[0]=(hb0? v[2]:v[0])+r;
            v[1]=v[1]+r2;
        }

        if(half){   // end scores -> gmem
            const int s=r0+rowown;
            g_end[s*8+down]=v[0];
            if(!hb0) g_end[s*8+down+1]=v[1];
        } else {    // start scores -> warp smem handoff
            sbuf[w][rowown*6+down]=v[0];
            if(!hb0) sbuf[w][rowown*6+down+1]=v[1];
        }
        __syncwarp();
        if(lane<TT){
            #pragma unroll
            for(int r=0;r<4;r++){
                float x=sbuf[w][r*6+lane];
                zv += __expf(x);
                const int idx=r0+r;
                if     (better(x,idx,v0,i0)){ v2=v1;i2=i1; v1=v0;i1=i0; v0=x;i0=idx; }
                else if(better(x,idx,v1,i1)){ v2=v1;i2=i1; v1=x; i1=idx; }
                else if(better(x,idx,v2,i2)){ v2=x; i2=idx; }
            }
        }
        __syncwarp();
    }

    // ---- per-CTA epilogue ----
    if(lane<TT){
        sZ[w][lane]=zv;
        sT3v[w][lane][0]=v0; sT3v[w][lane][1]=v1; sT3v[w][lane][2]=v2;
        sT3i[w][lane][0]=i0; sT3i[w][lane][1]=i1; sT3i[w][lane][2]=i2;
    }
    __syncthreads();                 // weights done -> reuse sW as 12-slot pool staging

    // pool staging: warps 0-11 store, warps 12-15 add
    const int pbase = half*384 + (hl<<2);
    if(w<12){
        #pragma unroll
        for(int p=0;p<6;p++){
            ulonglong2 u; u.x=pool[2*p]; u.y=pool[2*p+1];
            *reinterpret_cast<ulonglong2*>(&sW[w*HDIM + pbase + p*64]) = u;
        }
    }
    __syncthreads();
    if(w>=12){
        #pragma unroll
        for(int p=0;p<6;p++){
            float* dst = &sW[(w-12)*HDIM + pbase + p*64];
            dst[0]+=lo2(pool[2*p]); dst[1]+=hi2(pool[2*p]);
            dst[2]+=lo2(pool[2*p+1]); dst[3]+=hi2(pool[2*p+1]);
        }
    }
    __syncthreads();
    for(int h=tid;h<HDIM;h+=NTHREAD){
        float s=0.f;
        #pragma unroll
        for(int ww=0;ww<12;ww++) s+=sW[ww*HDIM+h];
        sW[h]=s;                      // raw pooled partial (unscaled)
    }
    __syncthreads();
    {   // W1 GEMV partial: u owns output col, 8 slices of 96 h
        const int u=tid&63, sl=tid>>6;
        float acc=0.f;
        const int h0=sl*96;
        #pragma unroll 4
        for(int h=h0;h<h0+96;h++) acc += sW[h]*W1[h*64+u];
        yred[tid]=acc;
    }
    __syncthreads();
    if(tid<64){
        float y=0.f;
        #pragma unroll
        for(int s=0;s<8;s++) y+=yred[tid+64*s];
        g_y[blockIdx.x*64+tid]=y;
    }
    if(tid<TT){
        float Z=0.f;
        #pragma unroll
        for(int ww=0;ww<NWARP;ww++) Z+=sZ[ww][tid];
        g_z[blockIdx.x*TT+tid]=Z;

        float m0=-3.4e38f,m1=-3.4e38f,m2=-3.4e38f;
        int   j0=0x7fffffff,j1=0x7fffffff,j2=0x7fffffff;
        #pragma unroll
        for(int ww=0;ww<NWARP;ww++){
            #pragma unroll
            for(int k=0;k<3;k++){
                float x=sT3v[ww][tid][k]; int id=sT3i[ww][tid][k];
                INS3(x,id);
            }
        }
        const int bo=(blockIdx.x*TT+tid)*3;
        g_t3v[bo  ]=m0; g_t3v[bo+1]=m1; g_t3v[bo+2]=m2;
        g_t3i[bo  ]=j0; g_t3i[bo+1]=j1; g_t3i[bo+2]=j2;
    }

    // ---- last-block final phase ----
    __threadfence();
    __syncthreads();
    if(tid==0) slast = atomicAdd(&g_ctr,1);
    __syncthreads();
    if(slast != GRID1-1) return;

    for(int i=tid;i<out_size;i+=NTHREAD) out[i]=0.f;
    {   // reduce y partials over 152 blocks
        const int u=tid&63, sl=tid>>6;
        float s=0.f;
        for(int b=sl;b<GRID1;b+=8) s+=g_y[b*64+u];
        yred[tid]=s;
    }
    __syncthreads();
    if(tid<64){
        float yt=0.f;
        #pragma unroll
        for(int s=0;s<8;s++) yt+=yred[tid+64*s];
        float aa = yt*(1.f/(float)S_TOK) + b1[tid];
        hbuf[tid]=0.5f*aa*(1.f+erff(aa*0.70710678118654752f));
    } else if(w>=2 && w<8){
        const int t=w-2;
        float Z=0.f;
        float m0=-3.4e38f,m1=-3.4e38f,m2=-3.4e38f;
        int   j0=0x7fffffff,j1=0x7fffffff,j2=0x7fffffff;
        for(int b=lane;b<GRID1;b+=32){
            Z += g_z[b*TT+t];
            #pragma unroll
            for(int k=0;k<3;k++){
                float x=g_t3v[(b*TT+t)*3+k]; int id=g_t3i[(b*TT+t)*3+k];
                INS3(x,id);
            }
        }
        #pragma unroll
        for(int off=16;off>0;off>>=1){
            Z += __shfl_xor_sync(0xffffffffu,Z,off);
            float u0=__shfl_xor_sync(0xffffffffu,m0,off); int q0=__shfl_xor_sync(0xffffffffu,j0,off);
            float u1=__shfl_xor_sync(0xffffffffu,m1,off); int q1=__shfl_xor_sync(0xffffffffu,j1,off);
            float u2=__shfl_xor_sync(0xffffffffu,m2,off); int q2=__shfl_xor_sync(0xffffffffu,j2,off);
            INS3(u0,q0); INS3(u1,q1); INS3(u2,q2);
        }
        if(lane==0){
            fZ[t]=Z;
            fV[t][0]=m0; fV[t][1]=m1; fV[t][2]=m2;
            fI[t][0]=j0; fI[t][1]=j1; fI[t][2]=j2;
        }
    }
    __syncthreads();
    if(tid<TT){
        float z=b2[tid];
        #pragma unroll
        for(int j=0;j<64;j++) z+=hbuf[j]*W2[j*TT+tid];
        tc[tid]=1.f/(1.f+expf(-z));
    }
    __syncthreads();
    if(tid<TT*KK){
        const int t=tid/KK, k=tid-t*KK;
        const int idx=fI[t][k];
        const float p=__expf(fV[t][k])/fZ[t];

        float best=-3.4e38f; int off=0;
        #pragma unroll
        for(int wv=0;wv<WIN;wv++){
            int pos=idx+wv;
            if(pos<S_TOK){
                float e=g_end[pos*8+t];
                if(e>best){ best=e; off=wv; }
            }
        }
        const bool valid=(tc[t]>=0.3f)&&(p>=0.15f);
        const float c=valid? p*tc[t] : 0.f;
        const int base=t*KK+k;
        if(base      < out_size) out[base]      = c;
        if(18+base   < out_size) out[18+base]   = (float)idx;
        if(36+base   < out_size) out[36+base]   = (float)(idx+off+1);
        if(54+base   < out_size) out[54+base]   = valid? 1.f:0.f;
    }
    __syncthreads();
    if(tid==0) g_ctr=0u;    // reset for next graph replay
}

extern "C" void kernel_launch(void* const* d_in, const int* in_sizes, int n_in,
                              void* d_out, int out_size)
{
    const float* emb = (const float*)d_in[0];
    const float* Wst = (const float*)d_in[1];
    const float* Wen = (const float*)d_in[3];
    const float* W1  = (const float*)d_in[5];
    const float* b1  = (const float*)d_in[6];
    const float* W2  = (const float*)d_in[7];
    const float* b2  = (const float*)d_in[8];

    k1<<<GRID1, NTHREAD>>>(emb, Wst, Wen, W1, b1, W2, b2, (float*)d_out, out_size);
}

// round 6
// speedup vs baseline: 1.0006x; 1.0006x over previous
#include <cuda_runtime.h>
#include <cstdint>
#include <cstddef>

#define S_TOK 65536
#define HDIM 768
#define TT 6
#define KK 3
#define WIN 15
#define GRID1 152
#define NTHREAD 512
#define NWARP 16
#define GROUPS (S_TOK/4)

// ---- static scratch ----
__device__ float g_end [S_TOK*8];       // end scores, [s][t] padded to 8
__device__ float g_z  [GRID1*TT];       // per-block sum exp(x)
__device__ float g_t3v[GRID1*TT*3];
__device__ int   g_t3i[GRID1*TT*3];
__device__ float g_y  [GRID1*64];       // per-block W1 GEMV partials (unscaled)
__device__ unsigned g_ctr;

__device__ __forceinline__ void fma2(unsigned long long &d, unsigned long long a, unsigned long long b){
    asm("fma.rn.f32x2 %0, %1, %2, %0;" : "+l"(d) : "l"(a), "l"(b));
}
__device__ __forceinline__ float lo2(unsigned long long u){ return __uint_as_float((unsigned)(u & 0xffffffffull)); }
__device__ __forceinline__ float hi2(unsigned long long u){ return __uint_as_float((unsigned)(u >> 32)); }
__device__ __forceinline__ bool better(float v,int i,float V,int I){ return (v>V)||(v==V && i<I); }
__device__ __forceinline__ void pfL2(const void* p){
    asm volatile("prefetch.global.L2 [%0];" :: "l"(p));
}
// predicated packed pool accumulate (no divergence, no BSSY)
__device__ __forceinline__ void pooladd(unsigned long long &p0, unsigned long long &p1,
    unsigned long long c0x, unsigned long long c0y, unsigned long long c1x, unsigned long long c1y,
    unsigned long long c2x, unsigned long long c2y, unsigned long long c3x, unsigned long long c3y,
    unsigned take)
{
    asm volatile("{\n\t.reg .pred p;\n\tsetp.ne.u32 p, %10, 0;\n\t"
      "@p add.rn.f32x2 %0, %0, %2;\n\t@p add.rn.f32x2 %0, %0, %4;\n\t"
      "@p add.rn.f32x2 %0, %0, %6;\n\t@p add.rn.f32x2 %0, %0, %8;\n\t"
      "@p add.rn.f32x2 %1, %1, %3;\n\t@p add.rn.f32x2 %1, %1, %5;\n\t"
      "@p add.rn.f32x2 %1, %1, %7;\n\t@p add.rn.f32x2 %1, %1, %9;\n\t}"
      : "+l"(p0), "+l"(p1)
      : "l"(c0x),"l"(c0y),"l"(c1x),"l"(c1y),"l"(c2x),"l"(c2y),"l"(c3x),"l"(c3y),"r"(take));
}

#define INS3(x,id) do{ \
    if     (better((x),(id),m0,j0)){ m2=m1;j2=j1; m1=m0;j1=j0; m0=(x);j0=(id); } \
    else if(better((x),(id),m1,j1)){ m2=m1;j2=j1; m1=(x);j1=(id); } \
    else if(better((x),(id),m2,j2)){ m2=(x);j2=(id); } }while(0)

__global__ __launch_bounds__(NTHREAD,1) void k1(
    const float* __restrict__ emb, const float* __restrict__ Wst,
    const float* __restrict__ Wen, const float* __restrict__ W1,
    const float* __restrict__ b1,  const float* __restrict__ W2,
    const float* __restrict__ b2,  float* __restrict__ out, int out_size)
{
    __shared__ __align__(16) float sW[12*HDIM];   // weights; later reused as pool staging (12 slots)
    __shared__ float sbuf[NWARP][24];
    __shared__ float sZ[NWARP][TT];
    __shared__ float sT3v[NWARP][TT][3];
    __shared__ int   sT3i[NWARP][TT][3];
    __shared__ float yred[NTHREAD];
    __shared__ float hbuf[64];
    __shared__ float tc[TT], fZ[TT], fV[TT][3];
    __shared__ int   fI[TT][3];
    __shared__ unsigned slast;

    const int tid = threadIdx.x, w = tid>>5, lane = tid&31;
    const int half = lane>>4, hl = lane&15;
    const int hb3=(hl>>3)&1, hb2=(hl>>2)&1, hb1=(hl>>1)&1, hb0=hl&1;
    const int rowown = hb3*2+hb2;
    const int down   = hb1*3 + (hb0?2:0);
    const unsigned take0 = (half==0)?1u:0u, take1 = 1u-take0;

    // weights transposed: sW[d*768+h]; d 0..5 start, 6..11 end
    for(int i=tid;i<HDIM*TT;i+=NTHREAD){
        int h=i/TT, t=i-h*TT;
        sW[t*HDIM+h]      = Wst[i];
        sW[(TT+t)*HDIM+h] = Wen[i];
    }
    __syncthreads();

    unsigned long long pool[12];
    #pragma unroll
    for(int i=0;i<12;i++) pool[i]=0ull;
    float zv=0.f;
    float v0=-3.4e38f,v1=-3.4e38f,v2=-3.4e38f;
    int i0=0x7fffffff,i1=0x7fffffff,i2=0x7fffffff;

    const float* wbase = sW + (half*6)*HDIM + (hl<<2);
    const int gw = blockIdx.x*NWARP + w;
    const int nw = GRID1*NWARP;

    for(int g=gw; g<GROUPS; g+=nw){
        const int r0=g*4;
        const float* cb = emb + (size_t)g*(4*HDIM) + (hl<<2);
        const int gn = (g+nw<GROUPS)? g+nw : g;
        const float* nb = emb + (size_t)gn*(4*HDIM) + (hl<<2);

        #pragma unroll
        for(int c=0;c<12;c++){
            pfL2(nb + c*64);
            pfL2(nb + HDIM   + c*64);
            pfL2(nb + 2*HDIM + c*64);
            pfL2(nb + 3*HDIM + c*64);
        }

        unsigned long long a[24];
        #pragma unroll
        for(int i=0;i<24;i++) a[i]=0ull;

        #pragma unroll
        for(int c=0;c<12;c++){
            const float* cp = cb + c*64;
            ulonglong2 C0=*(const ulonglong2*)(cp);
            ulonglong2 C1=*(const ulonglong2*)(cp+HDIM);
            ulonglong2 C2=*(const ulonglong2*)(cp+2*HDIM);
            ulonglong2 C3=*(const ulonglong2*)(cp+3*HDIM);

            const int pidx = (c<6)? c : c-6;
            pooladd(pool[2*pidx], pool[2*pidx+1],
                    C0.x,C0.y, C1.x,C1.y, C2.x,C2.y, C3.x,C3.y,
                    (c<6)? take0 : take1);

            const float* wp = wbase + c*64;
            #pragma unroll
            for(int dd=0;dd<6;dd++){
                ulonglong2 W=*(const ulonglong2*)(wp + dd*HDIM);
                fma2(a[dd],    C0.x,W.x); fma2(a[dd],    C0.y,W.y);
                fma2(a[6+dd],  C1.x,W.x); fma2(a[6+dd],  C1.y,W.y);
                fma2(a[12+dd], C2.x,W.x); fma2(a[12+dd], C2.y,W.y);
                fma2(a[18+dd], C3.x,W.x); fma2(a[18+dd], C3.y,W.y);
            }
        }

        float v[24];
        #pragma unroll
        for(int i=0;i<24;i++) v[i]=lo2(a[i])+hi2(a[i]);

        // 16-lane ragged butterfly: 24 -> 12 -> 6 -> 3 -> {2,1}
        #pragma unroll
        for(int i=0;i<12;i++){ float s=hb3? v[i]:v[i+12]; float r=__shfl_xor_sync(0xffffffffu,s,8); v[i]=(hb3? v[i+12]:v[i])+r; }
        #pragma unroll
        for(int i=0;i<6;i++){  float s=hb2? v[i]:v[i+6];  float r=__shfl_xor_sync(0xffffffffu,s,4); v[i]=(hb2? v[i+6]:v[i])+r; }
        #pragma unroll
        for(int i=0;i<3;i++){  float s=hb1? v[i]:v[i+3];  float r=__shfl_xor_sync(0xffffffffu,s,2); v[i]=(hb1? v[i+3]:v[i])+r; }
        {
            float s =hb0? v[0]:v[2]; float r =__shfl_xor_sync(0xffffffffu,s,1);
            float r2=__shfl_xor_sync(0xffffffffu,v[1],1);
            v[0]=(hb0? v[2]:v[0])+r;
            v[1]=v[1]+r2;
        }

        if(half){   // end scores -> gmem
            const int s=r0+rowown;
            g_end[s*8+down]=v[0];
            if(!hb0) g_end[s*8+down+1]=v[1];
        } else {    // start scores -> warp smem handoff
            sbuf[w][rowown*6+down]=v[0];
            if(!hb0) sbuf[w][rowown*6+down+1]=v[1];
        }
        __syncwarp();
        if(lane<TT){
            #pragma unroll
            for(int r=0;r<4;r++){
                float x=sbuf[w][r*6+lane];
                zv += __expf(x);
                const int idx=r0+r;
                if     (better(x,idx,v0,i0)){ v2=v1;i2=i1; v1=v0;i1=i0; v0=x;i0=idx; }
                else if(better(x,idx,v1,i1)){ v2=v1;i2=i1; v1=x; i1=idx; }
                else if(better(x,idx,v2,i2)){ v2=x; i2=idx; }
            }
        }
        __syncwarp();
    }

    // ---- per-CTA epilogue ----
    if(lane<TT){
        sZ[w][lane]=zv;
        sT3v[w][lane][0]=v0; sT3v[w][lane][1]=v1; sT3v[w][lane][2]=v2;
        sT3i[w][lane][0]=i0; sT3i[w][lane][1]=i1; sT3i[w][lane][2]=i2;
    }
    __syncthreads();                 // weights done -> reuse sW as 12-slot pool staging

    // pool staging: warps 0-11 store, warps 12-15 add
    const int pbase = half*384 + (hl<<2);
    if(w<12){
        #pragma unroll
        for(int p=0;p<6;p++){
            ulonglong2 u; u.x=pool[2*p]; u.y=pool[2*p+1];
            *reinterpret_cast<ulonglong2*>(&sW[w*HDIM + pbase + p*64]) = u;
        }
    }
    __syncthreads();
    if(w>=12){
        #pragma unroll
        for(int p=0;p<6;p++){
            float* dst = &sW[(w-12)*HDIM + pbase + p*64];
            dst[0]+=lo2(pool[2*p]); dst[1]+=hi2(pool[2*p]);
            dst[2]+=lo2(pool[2*p+1]); dst[3]+=hi2(pool[2*p+1]);
        }
    }
    __syncthreads();
    for(int h=tid;h<HDIM;h+=NTHREAD){
        float s=0.f;
        #pragma unroll
        for(int ww=0;ww<12;ww++) s+=sW[ww*HDIM+h];
        sW[h]=s;                      // raw pooled partial (unscaled)
    }
    __syncthreads();
    {   // W1 GEMV partial: u owns output col, 8 slices of 96 h
        const int u=tid&63, sl=tid>>6;
        float acc=0.f;
        const int h0=sl*96;
        #pragma unroll 4
        for(int h=h0;h<h0+96;h++) acc += sW[h]*W1[h*64+u];
        yred[tid]=acc;
    }
    __syncthreads();
    if(tid<64){
        float y=0.f;
        #pragma unroll
        for(int s=0;s<8;s++) y+=yred[tid+64*s];
        g_y[blockIdx.x*64+tid]=y;
    }
    if(tid<TT){
        float Z=0.f;
        #pragma unroll
        for(int ww=0;ww<NWARP;ww++) Z+=sZ[ww][tid];
        g_z[blockIdx.x*TT+tid]=Z;

        float m0=-3.4e38f,m1=-3.4e38f,m2=-3.4e38f;
        int   j0=0x7fffffff,j1=0x7fffffff,j2=0x7fffffff;
        #pragma unroll
        for(int ww=0;ww<NWARP;ww++){
            #pragma unroll
            for(int k=0;k<3;k++){
                float x=sT3v[ww][tid][k]; int id=sT3i[ww][tid][k];
                INS3(x,id);
            }
        }
        const int bo=(blockIdx.x*TT+tid)*3;
        g_t3v[bo  ]=m0; g_t3v[bo+1]=m1; g_t3v[bo+2]=m2;
        g_t3i[bo  ]=j0; g_t3i[bo+1]=j1; g_t3i[bo+2]=j2;
    }

    // ---- last-block final phase ----
    __threadfence();
    __syncthreads();
    if(tid==0) slast = atomicAdd(&g_ctr,1);
    __syncthreads();
    if(slast != GRID1-1) return;

    for(int i=tid;i<out_size;i+=NTHREAD) out[i]=0.f;
    {   // reduce y partials over 152 blocks
        const int u=tid&63, sl=tid>>6;
        float s=0.f;
        for(int b=sl;b<GRID1;b+=8) s+=g_y[b*64+u];
        yred[tid]=s;
    }
    __syncthreads();
    if(tid<64){
        float yt=0.f;
        #pragma unroll
        for(int s=0;s<8;s++) yt+=yred[tid+64*s];
        float aa = yt*(1.f/(float)S_TOK) + b1[tid];
        hbuf[tid]=0.5f*aa*(1.f+erff(aa*0.70710678118654752f));
    } else if(w>=2 && w<8){
        const int t=w-2;
        float Z=0.f;
        float m0=-3.4e38f,m1=-3.4e38f,m2=-3.4e38f;
        int   j0=0x7fffffff,j1=0x7fffffff,j2=0x7fffffff;
        for(int b=lane;b<GRID1;b+=32){
            Z += g_z[b*TT+t];
            #pragma unroll
            for(int k=0;k<3;k++){
                float x=g_t3v[(b*TT+t)*3+k]; int id=g_t3i[(b*TT+t)*3+k];
                INS3(x,id);
            }
        }
        #pragma unroll
        for(int off=16;off>0;off>>=1){
            Z += __shfl_xor_sync(0xffffffffu,Z,off);
            float u0=__shfl_xor_sync(0xffffffffu,m0,off); int q0=__shfl_xor_sync(0xffffffffu,j0,off);
            float u1=__shfl_xor_sync(0xffffffffu,m1,off); int q1=__shfl_xor_sync(0xffffffffu,j1,off);
            float u2=__shfl_xor_sync(0xffffffffu,m2,off); int q2=__shfl_xor_sync(0xffffffffu,j2,off);
            INS3(u0,q0); INS3(u1,q1); INS3(u2,q2);
        }
        if(lane==0){
            fZ[t]=Z;
            fV[t][0]=m0; fV[t][1]=m1; fV[t][2]=m2;
            fI[t][0]=j0; fI[t][1]=j1; fI[t][2]=j2;
        }
    }
    __syncthreads();
    if(tid<TT){
        float z=b2[tid];
        #pragma unroll
        for(int j=0;j<64;j++) z+=hbuf[j]*W2[j*TT+tid];
        tc[tid]=1.f/(1.f+expf(-z));
    }
    __syncthreads();
    if(tid<TT*KK){
        const int t=tid/KK, k=tid-t*KK;
        const int idx=fI[t][k];
        const float p=__expf(fV[t][k])/fZ[t];

        float best=-3.4e38f; int off=0;
        #pragma unroll
        for(int wv=0;wv<WIN;wv++){
            int pos=idx+wv;
            if(pos<S_TOK){
                float e=g_end[pos*8+t];
                if(e>best){ best=e; off=wv; }
            }
        }
        const bool valid=(tc[t]>=0.3f)&&(p>=0.15f);
        const float c=valid? p*tc[t] : 0.f;
        const int base=t*KK+k;
        if(base      < out_size) out[base]      = c;
        if(18+base   < out_size) out[18+base]   = (float)idx;
        if(36+base   < out_size) out[36+base]   = (float)(idx+off+1);
        if(54+base   < out_size) out[54+base]   = valid? 1.f:0.f;
    }
    __syncthreads();
    if(tid==0) g_ctr=0u;    // reset for next graph replay
}

extern "C" void kernel_launch(void* const* d_in, const int* in_sizes, int n_in,
                              void* d_out, int out_size)
{
    const float* emb = (const float*)d_in[0];
    const float* Wst = (const float*)d_in[1];
    const float* Wen = (const float*)d_in[3];
    const float* W1  = (const float*)d_in[5];
    const float* b1  = (const float*)d_in[6];
    const float* W2  = (const float*)d_in[7];
    const float* b2  = (const float*)d_in[8];

    k1<<<GRID1, NTHREAD>>>(emb, Wst, Wen, W1, b1, W2, b2, (float*)d_out, out_size);
}

// round 10
// speedup vs baseline: 1.2367x; 1.2359x over previous
#include <cuda_runtime.h>
#include <cstdint>
#include <cstddef>

#define S_TOK 65536
#define HDIM 768
#define TT 6
#define KK 3
#define WIN 15
#define GRID1 152
#define NTHREAD 512
#define NWARP 16
#define NPAIR 8
#define GROUPS (S_TOK/4)

// ---- static scratch ----
__device__ float g_end [S_TOK*8];       // end scores, [s][t] padded to 8
__device__ float g_z  [GRID1*TT];
__device__ float g_t3v[GRID1*TT*3];
__device__ int   g_t3i[GRID1*TT*3];
__device__ float g_y  [GRID1*64];       // per-block W1 GEMV partials (unscaled)
__device__ unsigned g_ctr;

typedef unsigned long long ull;

__device__ __forceinline__ void fma2(ull &d, ull a, ull b){
    asm("fma.rn.f32x2 %0, %1, %2, %0;" : "+l"(d) : "l"(a), "l"(b));
}
__device__ __forceinline__ void add8(ull &p0, ull &p1,
    ull c0x, ull c0y, ull c1x, ull c1y, ull c2x, ull c2y, ull c3x, ull c3y)
{
    asm("add.rn.f32x2 %0, %0, %2;\n\tadd.rn.f32x2 %0, %0, %4;\n\t"
        "add.rn.f32x2 %0, %0, %6;\n\tadd.rn.f32x2 %0, %0, %8;\n\t"
        "add.rn.f32x2 %1, %1, %3;\n\tadd.rn.f32x2 %1, %1, %5;\n\t"
        "add.rn.f32x2 %1, %1, %7;\n\tadd.rn.f32x2 %1, %1, %9;"
        : "+l"(p0), "+l"(p1)
        : "l"(c0x),"l"(c0y),"l"(c1x),"l"(c1y),"l"(c2x),"l"(c2y),"l"(c3x),"l"(c3y));
}
__device__ __forceinline__ float lo2(ull u){ return __uint_as_float((unsigned)(u & 0xffffffffull)); }
__device__ __forceinline__ float hi2(ull u){ return __uint_as_float((unsigned)(u >> 32)); }
__device__ __forceinline__ bool better(float v,int i,float V,int I){ return (v>V)||(v==V && i<I); }
__device__ __forceinline__ void pfL2(const void* p){
    asm volatile("prefetch.global.L2 [%0];" :: "l"(p));
}

#define INS3(x,id) do{ \
    if     (better((x),(id),m0,j0)){ m2=m1;j2=j1; m1=m0;j1=j0; m0=(x);j0=(id); } \
    else if(better((x),(id),m1,j1)){ m2=m1;j2=j1; m1=(x);j1=(id); } \
    else if(better((x),(id),m2,j2)){ m2=(x);j2=(id); } }while(0)

__global__ __launch_bounds__(NTHREAD,1) void k1(
    const float* __restrict__ emb, const float* __restrict__ Wst,
    const float* __restrict__ Wen, const float* __restrict__ W1,
    const float* __restrict__ b1,  const float* __restrict__ W2,
    const float* __restrict__ b2,  float* __restrict__ out, int out_size)
{
    __shared__ __align__(16) float sW[12*HDIM];   // weights; later reused for pool staging
    __shared__ float sbuf[NWARP][24];
    __shared__ float sZ[NWARP][TT];
    __shared__ float sT3v[NWARP][TT][3];
    __shared__ int   sT3i[NWARP][TT][3];
    __shared__ float yred[NTHREAD];
    __shared__ float hbuf[64];
    __shared__ float tc[TT], fZ[TT], fV[TT][3];
    __shared__ int   fI[TT][3];
    __shared__ unsigned slast;

    const int tid = threadIdx.x, w = tid>>5, lane = tid&31;
    const int pair = w>>1;
    const int is_end = w&1;          // warp-uniform
    const int l4=(lane>>4)&1, l3=(lane>>3)&1, l2=(lane>>2)&1, l1=(lane>>1)&1, l0=lane&1;
    const int rowown = l4*2+l3;
    const int down   = l2*3 + (l1?2:0);   // dim owned in v[0]
    const int down1  = l2*3 + 1;          // dim owned in v[1]

    // weights transposed: sW[d*768+h]; d 0..5 start, 6..11 end
    for(int i=tid;i<HDIM*TT;i+=NTHREAD){
        int h=i/TT, t=i-h*TT;
        sW[t*HDIM+h]      = Wst[i];
        sW[(TT+t)*HDIM+h] = Wen[i];
    }
    __syncthreads();

    ull pool[6];
    #pragma unroll
    for(int i=0;i<6;i++) pool[i]=0ull;
    float zv=0.f;
    float v0=-3.4e38f,v1=-3.4e38f,v2=-3.4e38f;
    int i0=0x7fffffff,i1=0x7fffffff,i2=0x7fffffff;

    const float* wbase = sW + (is_end*6)*HDIM + (lane<<2);
    const int gw = blockIdx.x*NPAIR + pair;
    const int nw = GRID1*NPAIR;

    // register-prefetch first group's chunk 0
    const float* bp0 = emb + (size_t)gw*(4*HDIM) + (lane<<2);
    ulonglong2 C0 = *(const ulonglong2*)(bp0);
    ulonglong2 C1 = *(const ulonglong2*)(bp0+HDIM);
    ulonglong2 C2 = *(const ulonglong2*)(bp0+2*HDIM);
    ulonglong2 C3 = *(const ulonglong2*)(bp0+3*HDIM);

    for(int g=gw; g<GROUPS; g+=nw){
        const int r0=g*4;
        const float* cb = emb + (size_t)g*(4*HDIM) + (lane<<2);
        const int gn = (g+nw<GROUPS)? g+nw : g;
        const float* nb = emb + (size_t)gn*(4*HDIM) + (lane<<2);

        // L2-prefetch next group, pair splits rows (2 rows x 6 chunks each)
        {
            const float* pf = nb + (is_end? 2*HDIM : 0);
            #pragma unroll
            for(int c=0;c<6;c++){ pfL2(pf + c*128); pfL2(pf + HDIM + c*128); }
        }

        ull a[24];
        #pragma unroll
        for(int i=0;i<24;i++) a[i]=0ull;

        #pragma unroll
        for(int j=0;j<6;j++){
            const float* np = (j<5)? (cb + (j+1)*128) : nb;
            ulonglong2 N0=*(const ulonglong2*)(np);
            ulonglong2 N1=*(const ulonglong2*)(np+HDIM);
            ulonglong2 N2=*(const ulonglong2*)(np+2*HDIM);
            ulonglong2 N3=*(const ulonglong2*)(np+3*HDIM);

            // pool: even warp takes chunks 0-2, odd takes 3-5 (warp-uniform branch)
            if((j<3) == (is_end==0)){
                const int pj = (j<3)? j : j-3;
                add8(pool[2*pj], pool[2*pj+1],
                     C0.x,C0.y, C1.x,C1.y, C2.x,C2.y, C3.x,C3.y);
            }

            const float* wp = wbase + j*128;
            #pragma unroll
            for(int dd=0;dd<6;dd++){
                ulonglong2 W=*(const ulonglong2*)(wp + dd*HDIM);
                fma2(a[dd],    C0.x,W.x); fma2(a[dd],    C0.y,W.y);
                fma2(a[6+dd],  C1.x,W.x); fma2(a[6+dd],  C1.y,W.y);
                fma2(a[12+dd], C2.x,W.x); fma2(a[12+dd], C2.y,W.y);
                fma2(a[18+dd], C3.x,W.x); fma2(a[18+dd], C3.y,W.y);
            }
            C0=N0; C1=N1; C2=N2; C3=N3;
        }

        float v[24];
        #pragma unroll
        for(int i=0;i<24;i++) v[i]=lo2(a[i])+hi2(a[i]);

        // 32-lane ragged butterfly: 24 -> 12 -> 6 -> 3 -> {2,1} -> complete
        #pragma unroll
        for(int i=0;i<12;i++){ float s=l4? v[i]:v[i+12]; float r=__shfl_xor_sync(0xffffffffu,s,16); v[i]=(l4? v[i+12]:v[i])+r; }
        #pragma unroll
        for(int i=0;i<6;i++){  float s=l3? v[i]:v[i+6];  float r=__shfl_xor_sync(0xffffffffu,s,8);  v[i]=(l3? v[i+6]:v[i])+r; }
        #pragma unroll
        for(int i=0;i<3;i++){  float s=l2? v[i]:v[i+3];  float r=__shfl_xor_sync(0xffffffffu,s,4);  v[i]=(l2? v[i+3]:v[i])+r; }
        {
            float s =l1? v[0]:v[2]; float r =__shfl_xor_sync(0xffffffffu,s,2);
            float r1=__shfl_xor_sync(0xffffffffu,v[1],2);
            v[0]=(l1? v[2]:v[0])+r;
            v[1]+=r1;
        }
        v[0]+=__shfl_xor_sync(0xffffffffu,v[0],1);
        v[1]+=__shfl_xor_sync(0xffffffffu,v[1],1);

        if(is_end){
            const int s=r0+rowown;
            if(!l0)        g_end[s*8+down ]=v[0];
            if(!l0 && !l1) g_end[s*8+down1]=v[1];
        } else {
            if(!l0)        sbuf[w][rowown*6+down ]=v[0];
            if(!l0 && !l1) sbuf[w][rowown*6+down1]=v[1];
        }
        __syncwarp();
        if(!is_end && lane<TT){
            #pragma unroll
            for(int r=0;r<4;r++){
                float x=sbuf[w][r*6+lane];
                zv += __expf(x);
                const int idx=r0+r;
                if     (better(x,idx,v0,i0)){ v2=v1;i2=i1; v1=v0;i1=i0; v0=x;i0=idx; }
                else if(better(x,idx,v1,i1)){ v2=v1;i2=i1; v1=x; i1=idx; }
                else if(better(x,idx,v2,i2)){ v2=x; i2=idx; }
            }
        }
        __syncwarp();
    }

    // ---- per-CTA epilogue ----
    if(!is_end && lane<TT){
        sZ[w][lane]=zv;
        sT3v[w][lane][0]=v0; sT3v[w][lane][1]=v1; sT3v[w][lane][2]=v2;
        sT3i[w][lane][0]=i0; sT3i[w][lane][1]=i1; sT3i[w][lane][2]=i2;
    }
    __syncthreads();                 // weights done -> reuse sW for pool staging (8 slots x 768)

    {   // each warp writes its 3 owned chunks into slot `pair`, halves disjoint
        float* slot = sW + pair*HDIM + (is_end? 384:0) + (lane<<2);
        #pragma unroll
        for(int p=0;p<3;p++){
            ulonglong2 u; u.x=pool[2*p]; u.y=pool[2*p+1];
            *reinterpret_cast<ulonglong2*>(slot + p*128) = u;
        }
    }
    __syncthreads();
    for(int h=tid;h<HDIM;h+=NTHREAD){
        float s=0.f;
        #pragma unroll
        for(int ww=0;ww<NPAIR;ww++) s+=sW[ww*HDIM+h];
        yred[ (h>=NTHREAD)? 0:0 ]=0.f; // no-op to keep compiler from reordering? (removed below)
        sW[h]=s;                      // safe: thread writing sW[h] is the only reader of slot-0[h] afterward
    }
    __syncthreads();
    {   // W1 GEMV partial: u owns output col, 8 slices of 96 h
        const int u=tid&63, sl=tid>>6;
        float acc=0.f;
        const int h0=sl*96;
        #pragma unroll 4
        for(int h=h0;h<h0+96;h++) acc += sW[h]*W1[h*64+u];
        yred[tid]=acc;
    }
    __syncthreads();
    if(tid<64){
        float y=0.f;
        #pragma unroll
        for(int s=0;s<8;s++) y+=yred[tid+64*s];
        g_y[blockIdx.x*64+tid]=y;
    }
    if(tid<TT){
        float Z=0.f;
        #pragma unroll
        for(int ww=0;ww<NWARP;ww+=2) Z+=sZ[ww][tid];
        g_z[blockIdx.x*TT+tid]=Z;

        float m0=-3.4e38f,m1=-3.4e38f,m2=-3.4e38f;
        int   j0=0x7fffffff,j1=0x7fffffff,j2=0x7fffffff;
        #pragma unroll
        for(int ww=0;ww<NWARP;ww+=2){
            #pragma unroll
            for(int k=0;k<3;k++){
                float x=sT3v[ww][tid][k]; int id=sT3i[ww][tid][k];
                INS3(x,id);
            }
        }
        const int bo=(blockIdx.x*TT+tid)*3;
        g_t3v[bo  ]=m0; g_t3v[bo+1]=m1; g_t3v[bo+2]=m2;
        g_t3i[bo  ]=j0; g_t3i[bo+1]=j1; g_t3i[bo+2]=j2;
    }

    // ---- last-block final phase ----
    __threadfence();
    __syncthreads();
    if(tid==0) slast = atomicAdd(&g_ctr,1);
    __syncthreads();
    if(slast != GRID1-1) return;

    for(int i=tid;i<out_size;i+=NTHREAD) out[i]=0.f;
    {   // reduce y partials over 152 blocks
        const int u=tid&63, sl=tid>>6;
        float s=0.f;
        for(int b=sl;b<GRID1;b+=8) s+=g_y[b*64+u];
        yred[tid]=s;
    }
    __syncthreads();
    if(tid<64){
        float yt=0.f;
        #pragma unroll
        for(int s=0;s<8;s++) yt+=yred[tid+64*s];
        float aa = yt*(1.f/(float)S_TOK) + b1[tid];
        hbuf[tid]=0.5f*aa*(1.f+erff(aa*0.70710678118654752f));
    } else if(w>=2 && w<8){
        const int t=w-2;
        float Z=0.f;
        float m0=-3.4e38f,m1=-3.4e38f,m2=-3.4e38f;
        int   j0=0x7fffffff,j1=0x7fffffff,j2=0x7fffffff;
        for(int b=lane;b<GRID1;b+=32){
            Z += g_z[b*TT+t];
            #pragma unroll
            for(int k=0;k<3;k++){
                float x=g_t3v[(b*TT+t)*3+k]; int id=g_t3i[(b*TT+t)*3+k];
                INS3(x,id);
            }
        }
        #pragma unroll
        for(int off=16;off>0;off>>=1){
            Z += __shfl_xor_sync(0xffffffffu,Z,off);
            float u0=__shfl_xor_sync(0xffffffffu,m0,off); int q0=__shfl_xor_sync(0xffffffffu,j0,off);
            float u1=__shfl_xor_sync(0xffffffffu,m1,off); int q1=__shfl_xor_sync(0xffffffffu,j1,off);
            float u2=__shfl_xor_sync(0xffffffffu,m2,off); int q2=__shfl_xor_sync(0xffffffffu,j2,off);
            INS3(u0,q0); INS3(u1,q1); INS3(u2,q2);
        }
        if(lane==0){
            fZ[t]=Z;
            fV[t][0]=m0; fV[t][1]=m1; fV[t][2]=m2;
            fI[t][0]=j0; fI[t][1]=j1; fI[t][2]=j2;
        }
    }
    __syncthreads();
    if(tid<TT){
        float z=b2[tid];
        #pragma unroll
        for(int j=0;j<64;j++) z+=hbuf[j]*W2[j*TT+tid];
        tc[tid]=1.f/(1.f+expf(-z));
    }
    __syncthreads();
    if(tid<TT*KK){
        const int t=tid/KK, k=tid-t*KK;
        const int idx=fI[t][k];
        const float p=__expf(fV[t][k])/fZ[t];

        float best=-3.4e38f; int off=0;
        #pragma unroll
        for(int wv=0;wv<WIN;wv++){
            int pos=idx+wv;
            if(pos<S_TOK){
                float e=g_end[pos*8+t];
                if(e>best){ best=e; off=wv; }
            }
        }
        const bool valid=(tc[t]>=0.3f)&&(p>=0.15f);
        const float c=valid? p*tc[t] : 0.f;
        const int base=t*KK+k;
        if(base      < out_size) out[base]      = c;
        if(18+base   < out_size) out[18+base]   = (float)idx;
        if(36+base   < out_size) out[36+base]   = (float)(idx+off+1);
        if(54+base   < out_size) out[54+base]   = valid? 1.f:0.f;
    }
    __syncthreads();
    if(tid==0) g_ctr=0u;    // reset for next graph replay
}

extern "C" void kernel_launch(void* const* d_in, const int* in_sizes, int n_in,
                              void* d_out, int out_size)
{
    const float* emb = (const float*)d_in[0];
    const float* Wst = (const float*)d_in[1];
    const float* Wen = (const float*)d_in[3];
    const float* W1  = (const float*)d_in[5];
    const float* b1  = (const float*)d_in[6];
    const float* W2  = (const float*)d_in[7];
    const float* b2  = (const float*)d_in[8];

    k1<<<GRID1, NTHREAD>>>(emb, Wst, Wen, W1, b1, W2, b2, (float*)d_out, out_size);
}